// round 1
// baseline (speedup 1.0000x reference)
#include <cuda_runtime.h>

#define NROWS 65536
#define DOUT  128
#define DLAT  64
#define DZ    64

// Global accumulators (no cudaMalloc allowed)
__device__ float g_scal[2];     // [0] = KL element sum A, [1] = recon sq-diff sum B
__device__ float g_col[5][DZ];  // Sz, Szt, Sz2, Szt2, Szp per column

__global__ void zero_kernel() {
    int t = threadIdx.x;
    if (t < 2) g_scal[t] = 0.0f;
    if (t < 5 * DZ) ((float*)g_col)[t] = 0.0f;
}

__global__ void __launch_bounds__(256) reduce_kernel(
    const float4* __restrict__ target,
    const float4* __restrict__ output,
    const float4* __restrict__ mean,
    const float4* __restrict__ logv,
    const float4* __restrict__ z,
    const float4* __restrict__ zt)
{
    const int tid = blockIdx.x * blockDim.x + threadIdx.x;
    const int T   = gridDim.x * blockDim.x;   // multiple of 16 guaranteed

    // ---- reconstruction: sum (o - t)^2 over N*128 ----
    float b = 0.0f;
    const int n_out4 = NROWS * DOUT / 4;
    for (int i = tid; i < n_out4; i += T) {
        float4 o = output[i], t4 = target[i];
        float d0 = o.x - t4.x, d1 = o.y - t4.y, d2 = o.z - t4.z, d3 = o.w - t4.w;
        b += d0 * d0 + d1 * d1 + d2 * d2 + d3 * d3;
    }

    // ---- KL: sum (lv - exp(lv) - m^2 + 1) over N*64 ----
    float a = 0.0f;
    const int n_lat4 = NROWS * DLAT / 4;
    for (int i = tid; i < n_lat4; i += T) {
        float4 lv = logv[i], m = mean[i];
        a += (lv.x - __expf(lv.x) - m.x * m.x + 1.0f);
        a += (lv.y - __expf(lv.y) - m.y * m.y + 1.0f);
        a += (lv.z - __expf(lv.z) - m.z * m.z + 1.0f);
        a += (lv.w - __expf(lv.w) - m.w * m.w + 1.0f);
    }

    // ---- z stats: per-column sums. Each row = 16 float4s; since T % 16 == 0,
    //      f4 index % 16 is constant per thread -> fixed 4 columns per thread.
    float sz[4]  = {0, 0, 0, 0};
    float szt[4] = {0, 0, 0, 0};
    float sz2[4] = {0, 0, 0, 0};
    float szt2[4]= {0, 0, 0, 0};
    float szp[4] = {0, 0, 0, 0};
    const int n_z4 = NROWS * DZ / 4;
    for (int i = tid; i < n_z4; i += T) {
        float4 u = z[i], v = zt[i];
        sz[0] += u.x; sz2[0] += u.x * u.x; szt[0] += v.x; szt2[0] += v.x * v.x; szp[0] += u.x * v.x;
        sz[1] += u.y; sz2[1] += u.y * u.y; szt[1] += v.y; szt2[1] += v.y * v.y; szp[1] += u.y * v.y;
        sz[2] += u.z; sz2[2] += u.z * u.z; szt[2] += v.z; szt2[2] += v.z * v.z; szp[2] += u.z * v.z;
        sz[3] += u.w; sz2[3] += u.w * u.w; szt[3] += v.w; szt2[3] += v.w * v.w; szp[3] += u.w * v.w;
    }

    // ---- block-level combine ----
    __shared__ float s_col[5][DZ];
    __shared__ float warp_a[8], warp_b[8];
    for (int i = threadIdx.x; i < 5 * DZ; i += blockDim.x)
        ((float*)s_col)[i] = 0.0f;
    __syncthreads();

    const int cg = threadIdx.x & 15;  // column group (same as tid % 16)
    #pragma unroll
    for (int c = 0; c < 4; c++) {
        int col = cg * 4 + c;
        atomicAdd(&s_col[0][col], sz[c]);
        atomicAdd(&s_col[1][col], szt[c]);
        atomicAdd(&s_col[2][col], sz2[c]);
        atomicAdd(&s_col[3][col], szt2[c]);
        atomicAdd(&s_col[4][col], szp[c]);
    }

    // scalar warp reduce
    #pragma unroll
    for (int off = 16; off; off >>= 1) {
        a += __shfl_down_sync(0xFFFFFFFFu, a, off);
        b += __shfl_down_sync(0xFFFFFFFFu, b, off);
    }
    if ((threadIdx.x & 31) == 0) {
        warp_a[threadIdx.x >> 5] = a;
        warp_b[threadIdx.x >> 5] = b;
    }
    __syncthreads();

    if (threadIdx.x == 0) {
        float ta = 0.0f, tb = 0.0f;
        #pragma unroll
        for (int w = 0; w < 8; w++) { ta += warp_a[w]; tb += warp_b[w]; }
        atomicAdd(&g_scal[0], ta);
        atomicAdd(&g_scal[1], tb);
    }
    for (int i = threadIdx.x; i < 5 * DZ; i += blockDim.x)
        atomicAdd(&((float*)g_col)[i], ((float*)s_col)[i]);
}

__global__ void finalize_kernel(float* __restrict__ out) {
    const int d = threadIdx.x;  // 0..63
    const float invN = 1.0f / (float)NROWS;

    float Sz   = g_col[0][d];
    float Szt  = g_col[1][d];
    float Sz2  = g_col[2][d];
    float Szt2 = g_col[3][d];
    float Szp  = g_col[4][d];

    float mu = Sz * invN, nu = Szt * invN;
    float cov  = Szp * invN - mu * nu;                                  // per-column centered mean product
    float vart = (Sz2  - (float)NROWS * mu * mu) / (float)(NROWS - 1);  // unbiased var (ddof=1)
    float varu = (Szt2 - (float)NROWS * nu * nu) / (float)(NROWS - 1);
    float sp = sqrtf(fmaxf(vart * varu, 0.0f));                         // std_t[d]*std_tau[d]

    #pragma unroll
    for (int off = 16; off; off >>= 1) {
        cov += __shfl_down_sync(0xFFFFFFFFu, cov, off);
        sp  += __shfl_down_sync(0xFFFFFFFFu, sp,  off);
    }
    __shared__ float sc[2], ss[2];
    if ((threadIdx.x & 31) == 0) { sc[threadIdx.x >> 5] = cov; ss[threadIdx.x >> 5] = sp; }
    __syncthreads();

    if (threadIdx.x == 0) {
        float num = sc[0] + sc[1];   // mean(diag)
        float dot = ss[0] + ss[1];   // dot(std_t, std_tau)
        float kl    = -0.5f * g_scal[0] * invN;
        float recon = g_scal[1] / (float)((long long)NROWS * DOUT);
        out[0] = recon + kl - num / dot;
    }
}

extern "C" void kernel_launch(void* const* d_in, const int* in_sizes, int n_in,
                              void* d_out, int out_size) {
    (void)in_sizes; (void)n_in; (void)out_size;
    const float4* target = (const float4*)d_in[0];
    const float4* output = (const float4*)d_in[1];
    const float4* mean   = (const float4*)d_in[2];
    const float4* logv   = (const float4*)d_in[3];
    const float4* z      = (const float4*)d_in[4];
    const float4* zt     = (const float4*)d_in[5];
    float* out = (float*)d_out;

    zero_kernel<<<1, 352>>>();
    reduce_kernel<<<1184, 256>>>(target, output, mean, logv, z, zt);
    finalize_kernel<<<1, 64>>>(out);
}

// round 2
// speedup vs baseline: 1.2853x; 1.2853x over previous
#include <cuda_runtime.h>

#define NROWS 65536
#define DOUT  128
#define DLAT  64
#define DZ    64

#define NBLOCKS 592          // 4 * 148 SMs -> one perfectly balanced wave
#define TPB     256
#define T_TOT   (NBLOCKS * TPB)   // 151552, multiple of 16

#define N_OUT4  (NROWS * DOUT / 4)   // 2097152
#define N_LAT4  (NROWS * DLAT / 4)   // 1048576
#define N_Z4    (NROWS * DZ   / 4)   // 1048576

// Zero-initialized device globals (reset by last block each call -> replay-safe)
__device__ float        g_scal[2];      // [0]=KL elem sum, [1]=recon sq sum
__device__ float        g_col[5][DZ];   // Sz, Szt, Sz2, Szt2, Szp
__device__ unsigned int g_count;

__global__ void __launch_bounds__(TPB, 4) vde_fused_kernel(
    const float4* __restrict__ target,
    const float4* __restrict__ output,
    const float4* __restrict__ mean,
    const float4* __restrict__ logv,
    const float4* __restrict__ z,
    const float4* __restrict__ zt,
    float* __restrict__ out)
{
    const int tid  = blockIdx.x * TPB + threadIdx.x;
    const int lane = threadIdx.x & 31;
    const int warp = threadIdx.x >> 5;

    // ---- reconstruction: sum (o - t)^2 ----
    float b = 0.0f;
    #pragma unroll 4
    for (int i = tid; i < N_OUT4; i += T_TOT) {
        float4 o  = __ldcs(output + i);
        float4 t4 = __ldcs(target + i);
        float d0 = o.x - t4.x, d1 = o.y - t4.y, d2 = o.z - t4.z, d3 = o.w - t4.w;
        b += d0 * d0 + d1 * d1;
        b += d2 * d2 + d3 * d3;
    }

    // ---- KL elements: sum (lv - exp(lv) - m^2 + 1) ----
    float a = 0.0f;
    #pragma unroll 4
    for (int i = tid; i < N_LAT4; i += T_TOT) {
        float4 lv = __ldcs(logv + i);
        float4 m  = __ldcs(mean + i);
        a += (lv.x - __expf(lv.x) - m.x * m.x + 1.0f);
        a += (lv.y - __expf(lv.y) - m.y * m.y + 1.0f);
        a += (lv.z - __expf(lv.z) - m.z * m.z + 1.0f);
        a += (lv.w - __expf(lv.w) - m.w * m.w + 1.0f);
    }

    // ---- z column stats. f4 index % 16 == tid % 16 (T_TOT % 16 == 0),
    //      so each thread owns 4 fixed columns: cg*4 .. cg*4+3 ----
    float st[5][4] = {{0}};   // [stat][col]: Sz, Szt, Sz2, Szt2, Szp
    #pragma unroll 2
    for (int i = tid; i < N_Z4; i += T_TOT) {
        float4 u = __ldcs(z  + i);
        float4 v = __ldcs(zt + i);
        st[0][0] += u.x; st[1][0] += v.x; st[2][0] += u.x * u.x; st[3][0] += v.x * v.x; st[4][0] += u.x * v.x;
        st[0][1] += u.y; st[1][1] += v.y; st[2][1] += u.y * u.y; st[3][1] += v.y * v.y; st[4][1] += u.y * v.y;
        st[0][2] += u.z; st[1][2] += v.z; st[2][2] += u.z * u.z; st[3][2] += v.z * v.z; st[4][2] += u.z * v.z;
        st[0][3] += u.w; st[1][3] += v.w; st[2][3] += u.w * u.w; st[3][3] += v.w * v.w; st[4][3] += u.w * v.w;
    }

    // ---- warp combine: lanes l and l+16 own the same columns ----
    #pragma unroll
    for (int s = 0; s < 5; s++)
        #pragma unroll
        for (int c = 0; c < 4; c++)
            st[s][c] += __shfl_xor_sync(0xFFFFFFFFu, st[s][c], 16);

    #pragma unroll
    for (int off = 16; off; off >>= 1) {
        a += __shfl_down_sync(0xFFFFFFFFu, a, off);
        b += __shfl_down_sync(0xFFFFFFFFu, b, off);
    }

    // ---- block combine via plain shared stores (no shared atomics) ----
    __shared__ float s_part[8][320];   // [warp][ (s*4+c)*16 + laneColGroup ]
    __shared__ float s_ab[8][2];

    if (lane < 16) {
        #pragma unroll
        for (int s = 0; s < 5; s++)
            #pragma unroll
            for (int c = 0; c < 4; c++)
                s_part[warp][(s * 4 + c) * 16 + lane] = st[s][c];
    }
    if (lane == 0) { s_ab[warp][0] = a; s_ab[warp][1] = b; }
    __syncthreads();

    for (int idx = threadIdx.x; idx < 320; idx += TPB) {
        float v = 0.0f;
        #pragma unroll
        for (int w = 0; w < 8; w++) v += s_part[w][idx];
        int s   = idx >> 6;          // stat
        int rem = idx & 63;
        int c   = rem >> 4;          // col offset within group
        int l   = rem & 15;          // col group
        atomicAdd(&g_col[s][l * 4 + c], v);
    }
    if (threadIdx.x == 0) {
        float ta = 0.0f, tb = 0.0f;
        #pragma unroll
        for (int w = 0; w < 8; w++) { ta += s_ab[w][0]; tb += s_ab[w][1]; }
        atomicAdd(&g_scal[0], ta);
        atomicAdd(&g_scal[1], tb);
    }

    // ---- last block finalizes + resets ----
    __shared__ unsigned int s_rank;
    __threadfence();
    __syncthreads();
    if (threadIdx.x == 0) s_rank = atomicAdd(&g_count, 1u);
    __syncthreads();
    if (s_rank != NBLOCKS - 1) return;

    __threadfence();   // acquire: other blocks' atomics visible

    __shared__ float sc[2], ss[2];
    if (threadIdx.x < DZ) {
        const int d = threadIdx.x;
        const float invN = 1.0f / (float)NROWS;
        float Sz   = *((volatile float*)&g_col[0][d]);
        float Szt  = *((volatile float*)&g_col[1][d]);
        float Sz2  = *((volatile float*)&g_col[2][d]);
        float Szt2 = *((volatile float*)&g_col[3][d]);
        float Szp  = *((volatile float*)&g_col[4][d]);

        float mu = Sz * invN, nu = Szt * invN;
        float cov  = Szp * invN - mu * nu;
        float vart = (Sz2  - (float)NROWS * mu * mu) / (float)(NROWS - 1);
        float varu = (Szt2 - (float)NROWS * nu * nu) / (float)(NROWS - 1);
        float sp = sqrtf(fmaxf(vart * varu, 0.0f));

        #pragma unroll
        for (int off = 16; off; off >>= 1) {
            cov += __shfl_down_sync(0xFFFFFFFFu, cov, off);
            sp  += __shfl_down_sync(0xFFFFFFFFu, sp,  off);
        }
        if (lane == 0) { sc[warp] = cov; ss[warp] = sp; }
    }
    __syncthreads();

    if (threadIdx.x == 0) {
        const float invN = 1.0f / (float)NROWS;
        float num = sc[0] + sc[1];                 // mean(diag)
        float dot = ss[0] + ss[1];                 // dot(std_t, std_tau)
        float kl    = -0.5f * (*((volatile float*)&g_scal[0])) * invN;
        float recon = (*((volatile float*)&g_scal[1])) / (float)((long long)NROWS * DOUT);
        out[0] = recon + kl - num / dot;
    }
    __syncthreads();   // reads done before reset

    // reset accumulators for next replay
    for (int i = threadIdx.x; i < 5 * DZ; i += TPB) ((float*)g_col)[i] = 0.0f;
    if (threadIdx.x == 0) { g_scal[0] = 0.0f; g_scal[1] = 0.0f; g_count = 0u; }
}

extern "C" void kernel_launch(void* const* d_in, const int* in_sizes, int n_in,
                              void* d_out, int out_size) {
    (void)in_sizes; (void)n_in; (void)out_size;
    vde_fused_kernel<<<NBLOCKS, TPB>>>(
        (const float4*)d_in[0], (const float4*)d_in[1],
        (const float4*)d_in[2], (const float4*)d_in[3],
        (const float4*)d_in[4], (const float4*)d_in[5],
        (float*)d_out);
}